// round 12
// baseline (speedup 1.0000x reference)
#include <cuda_runtime.h>

// InteractionLayer: out[b, idx(i,j)] = dot(x[b,i,:], x[b,j,:]) for j > i
// x: [4096, 64, 128] fp32,  out: [4096, 2016] fp32
//
// Round 11: first bench landed (90.6us, L1=88% fma=43% -> smem-crossbar bound).
// Upgrade 4x4 -> 8x8 register tiles: 16 LDS.128 per 256 FMA (2x arithmetic
// intensity vs smem) -> LDS traffic halves. fma floor ~37us, L1 floor ~43us.
//  - 4 batches per CTA, 160 threads, 144 active (36 triangular 8x8 tiles x4).
//  - smem swizzle at 8-row granularity: chunk = k4 ^ (f>>3); compute loads
//    conflict-free (bank group k4^bi / k4^bj distinct across warp), broadcast
//    within same tile-row; store phase is per-row permutation.

#define NUM_F      64
#define B_TOTAL    4096
#define OUT_PER_B  2016
#define THREADS    160
#define BATCHES    4
#define TILES      36           // 8*9/2 upper-triangular 8x8 tiles
#define ACTIVE     (BATCHES * TILES)   // 144
#define BATCH_F4   2048         // 64 rows * 32 float4 per batch
#define TOTAL_F4   (BATCHES * BATCH_F4)  // 8192

__global__ __launch_bounds__(THREADS)
void interaction_kernel8(const float* __restrict__ x, float* __restrict__ out) {
    extern __shared__ float4 s4[];          // 4 batches * 2048 float4 = 128 KB
    const int tid = threadIdx.x;
    const int b0  = blockIdx.x * BATCHES;

    // ---- cooperative load of 4 batches into swizzled smem ----
    const float4* g4 = reinterpret_cast<const float4*>(x) + (size_t)b0 * BATCH_F4;
    #pragma unroll 4
    for (int idx = tid; idx < TOTAL_F4; idx += THREADS) {
        int bb  = idx >> 11;            // / 2048
        int rem = idx & 2047;
        int f   = rem >> 5;             // feature row 0..63
        int k4  = rem & 31;             // float4 chunk along d
        s4[bb * BATCH_F4 + f * 32 + (k4 ^ (f >> 3))] = g4[idx];
    }
    __syncthreads();

    if (tid < ACTIVE) {
        const int bb = tid / TILES;
        const int t  = tid - bb * TILES;

        // decode t -> (bi, bj), bi <= bj, row-major over 8x8 tile grid
        int bi = 0, rem = t, cnt = 8;
        while (rem >= cnt) { rem -= cnt; ++bi; --cnt; }
        const int bj = bi + rem;

        const float4* sb = s4 + bb * BATCH_F4;
        const int i0 = 8 * bi, j0 = 8 * bj;

        float acc[8][8];
        #pragma unroll
        for (int r = 0; r < 8; ++r)
            #pragma unroll
            for (int s = 0; s < 8; ++s) acc[r][s] = 0.f;

        #pragma unroll 2
        for (int k4 = 0; k4 < 32; ++k4) {
            const int swi = k4 ^ bi;
            const int swj = k4 ^ bj;
            float4 a[8], e[8];
            #pragma unroll
            for (int r = 0; r < 8; ++r) a[r] = sb[(i0 + r) * 32 + swi];
            #pragma unroll
            for (int s = 0; s < 8; ++s) e[s] = sb[(j0 + s) * 32 + swj];

            #pragma unroll
            for (int r = 0; r < 8; ++r)
                #pragma unroll
                for (int s = 0; s < 8; ++s)
                    acc[r][s] = fmaf(a[r].x, e[s].x,
                                fmaf(a[r].y, e[s].y,
                                fmaf(a[r].z, e[s].z,
                                fmaf(a[r].w, e[s].w, acc[r][s]))));
        }

        // ---- write strictly-upper-triangular entries ----
        // idx(i,j) = i*63 - i*(i-1)/2 + (j - i - 1)
        float* ob = out + (size_t)(b0 + bb) * OUT_PER_B;
        if (bi != bj) {
            #pragma unroll
            for (int r = 0; r < 8; ++r) {
                const int i = i0 + r;
                const int base = i * 63 - (i * (i - 1)) / 2 - i - 1;  // + j
                #pragma unroll
                for (int s = 0; s < 8; ++s)
                    ob[base + j0 + s] = acc[r][s];
            }
        } else {
            #pragma unroll
            for (int r = 0; r < 8; ++r) {
                const int i = i0 + r;
                const int base = i * 63 - (i * (i - 1)) / 2 - i - 1;
                #pragma unroll
                for (int s = 0; s < 8; ++s) {
                    const int j = j0 + s;
                    if (j > i) ob[base + j] = acc[r][s];
                }
            }
        }
    }
}

extern "C" void kernel_launch(void* const* d_in, const int* in_sizes, int n_in,
                              void* d_out, int out_size) {
    (void)in_sizes; (void)n_in; (void)out_size;
    const float* x = (const float*)d_in[0];
    float* out = (float*)d_out;

    const int smem = TOTAL_F4 * sizeof(float4);   // 128 KB dynamic smem
    // Idempotent, deterministic, capture-safe: set every call (no static guards).
    cudaFuncSetAttribute(interaction_kernel8,
                         cudaFuncAttributeMaxDynamicSharedMemorySize, smem);
    interaction_kernel8<<<B_TOTAL / BATCHES, THREADS, smem>>>(x, out);
}

// round 13
// speedup vs baseline: 1.8643x; 1.8643x over previous
#include <cuda_runtime.h>

// InteractionLayer: out[b, idx(i,j)] = dot(x[b,i,:], x[b,j,:]) for j > i
// x: [4096, 64, 128] fp32,  out: [4096, 2016] fp32
//
// Round 13: 8x8 tiles kept (16:1 FMA:LDS, halves crossbar traffic vs 4x4
// baseline), but round-12's failure causes fixed:
//  - 2 batches/CTA (64 KB smem) -> 3 CTAs/SM = 9 warps/SM (was 1 CTA/5 warps)
//  - k-loop NOT unrolled -> live regs ~150, no spill (was unroll 2 -> 167 regs
//    + spills -> issue 35%)
// 96 threads, 72 active (36 triangular 8x8 tiles x 2 batches), grid 2048.

#define NUM_F      64
#define B_TOTAL    4096
#define OUT_PER_B  2016
#define THREADS    96
#define BATCHES    2
#define TILES      36           // 8*9/2 upper-triangular 8x8 tiles per batch
#define ACTIVE     (BATCHES * TILES)     // 72
#define BATCH_F4   2048         // 64 rows * 32 float4 per batch
#define TOTAL_F4   (BATCHES * BATCH_F4)  // 4096

__global__ __launch_bounds__(THREADS, 3)
void interaction_kernel8b(const float* __restrict__ x, float* __restrict__ out) {
    extern __shared__ float4 s4[];          // 2 batches * 2048 float4 = 64 KB
    const int tid = threadIdx.x;
    const int b0  = blockIdx.x * BATCHES;

    // ---- cooperative load of 2 batches into swizzled smem ----
    // swizzle at 8-row tile granularity: chunk = k4 ^ (f>>3)
    const float4* g4 = reinterpret_cast<const float4*>(x) + (size_t)b0 * BATCH_F4;
    for (int idx = tid; idx < TOTAL_F4; idx += THREADS) {
        int bb  = idx >> 11;            // / 2048
        int rem = idx & 2047;
        int f   = rem >> 5;             // feature row 0..63
        int k4  = rem & 31;             // float4 chunk along d
        s4[bb * BATCH_F4 + f * 32 + (k4 ^ (f >> 3))] = g4[idx];
    }
    __syncthreads();

    if (tid < ACTIVE) {
        const int bb = (tid >= TILES) ? 1 : 0;
        const int t  = tid - bb * TILES;

        // decode t -> (bi, bj), bi <= bj, row-major over 8x8 tile grid
        int bi = 0, rem = t, cnt = 8;
        while (rem >= cnt) { rem -= cnt; ++bi; --cnt; }
        const int bj = bi + rem;

        const float4* sb = s4 + bb * BATCH_F4;
        const int i0 = 8 * bi, j0 = 8 * bj;

        float acc[8][8];
        #pragma unroll
        for (int r = 0; r < 8; ++r)
            #pragma unroll
            for (int s = 0; s < 8; ++s) acc[r][s] = 0.f;

        #pragma unroll 1
        for (int k4 = 0; k4 < 32; ++k4) {
            const int swi = k4 ^ bi;
            const int swj = k4 ^ bj;
            float4 a[8], e[8];
            #pragma unroll
            for (int r = 0; r < 8; ++r) a[r] = sb[(i0 + r) * 32 + swi];
            #pragma unroll
            for (int s = 0; s < 8; ++s) e[s] = sb[(j0 + s) * 32 + swj];

            #pragma unroll
            for (int r = 0; r < 8; ++r)
                #pragma unroll
                for (int s = 0; s < 8; ++s)
                    acc[r][s] = fmaf(a[r].x, e[s].x,
                                fmaf(a[r].y, e[s].y,
                                fmaf(a[r].z, e[s].z,
                                fmaf(a[r].w, e[s].w, acc[r][s]))));
        }

        // ---- write strictly-upper-triangular entries ----
        // idx(i,j) = i*63 - i*(i-1)/2 + (j - i - 1)
        float* ob = out + (size_t)(b0 + bb) * OUT_PER_B;
        if (bi != bj) {
            #pragma unroll
            for (int r = 0; r < 8; ++r) {
                const int i = i0 + r;
                const int base = i * 63 - (i * (i - 1)) / 2 - i - 1;  // + j
                #pragma unroll
                for (int s = 0; s < 8; ++s)
                    ob[base + j0 + s] = acc[r][s];
            }
        } else {
            #pragma unroll
            for (int r = 0; r < 8; ++r) {
                const int i = i0 + r;
                const int base = i * 63 - (i * (i - 1)) / 2 - i - 1;
                #pragma unroll
                for (int s = 0; s < 8; ++s) {
                    const int j = j0 + s;
                    if (j > i) ob[base + j] = acc[r][s];
                }
            }
        }
    }
}

extern "C" void kernel_launch(void* const* d_in, const int* in_sizes, int n_in,
                              void* d_out, int out_size) {
    (void)in_sizes; (void)n_in; (void)out_size;
    const float* x = (const float*)d_in[0];
    float* out = (float*)d_out;

    const int smem = TOTAL_F4 * sizeof(float4);   // 64 KB dynamic smem
    // Idempotent, deterministic, capture-safe: set every call (no static guards).
    cudaFuncSetAttribute(interaction_kernel8b,
                         cudaFuncAttributeMaxDynamicSharedMemorySize, smem);
    interaction_kernel8b<<<B_TOTAL / BATCHES, THREADS, smem>>>(x, out);
}

// round 16
// speedup vs baseline: 2.5958x; 1.3924x over previous
#include <cuda_runtime.h>
#include <cstdint>

// InteractionLayer via mma.sync tf32 hi/lo split.
// out[b, idx(i,j)] = dot(x[b,i,:], x[b,j,:]), j > i.  x: [4096,64,128] f32.
// 1 warp = 1 batch: C = A·A^T (64x64) as 4x8 grid of m16n8k8 tiles, only
// tj >= 2*ti kept (20 tiles). Hi/lo tf32 split (3 MMAs) for fp32-grade error.
// B fragments are reused A-fragment registers (C = A·A^T symmetry) -> only
// 16 LDS.32 per k-step per warp, bank-conflict-free via ROW_STRIDE=132.

#define B_TOTAL    4096
#define OUT_PER_B  2016
#define THREADS    64
#define BATCHES    2
#define ROW_STRIDE 132                       // 128 + 4 pad floats
#define BATCH_SM   (64 * ROW_STRIDE)         // 8448 floats = 33792 B
#define NTILE      20

static __device__ __forceinline__ uint32_t f2tf32(float v) {
    uint32_t r;
    asm("cvt.rna.tf32.f32 %0, %1;" : "=r"(r) : "f"(v));
    return r;
}

static __device__ __forceinline__ void mma8(float* d, const uint32_t* a,
                                            uint32_t b0, uint32_t b1) {
    asm volatile(
        "mma.sync.aligned.m16n8k8.row.col.f32.tf32.tf32.f32 "
        "{%0,%1,%2,%3}, {%4,%5,%6,%7}, {%8,%9}, {%0,%1,%2,%3};"
        : "+f"(d[0]), "+f"(d[1]), "+f"(d[2]), "+f"(d[3])
        : "r"(a[0]), "r"(a[1]), "r"(a[2]), "r"(a[3]), "r"(b0), "r"(b1));
}

__global__ __launch_bounds__(THREADS, 3)
void interaction_mma(const float* __restrict__ x, float* __restrict__ out) {
    extern __shared__ float sm[];
    const int tid = threadIdx.x;
    const int b0  = blockIdx.x * BATCHES;

    // ---- cooperative load: 2 batches, coalesced float4, padded rows ----
    const float4* g4 = reinterpret_cast<const float4*>(x) + (size_t)b0 * 2048;
    for (int idx = tid; idx < BATCHES * 2048; idx += THREADS) {
        int bb = idx >> 11, rem = idx & 2047;
        int f  = rem >> 5,  c4  = rem & 31;
        *reinterpret_cast<float4*>(sm + bb * BATCH_SM + f * ROW_STRIDE + c4 * 4) =
            g4[idx];
    }
    __syncthreads();

    const int wid  = tid >> 5;
    const int lane = tid & 31;
    const int lr   = lane >> 2;    // 0..7
    const int lc   = lane & 3;     // 0..3
    float* sb = sm + wid * BATCH_SM;

    const int TOFF[4] = {0, 8, 14, 18};   // tile index offsets per ti

    float acc[NTILE][4];
    #pragma unroll
    for (int t = 0; t < NTILE; ++t) {
        acc[t][0] = acc[t][1] = acc[t][2] = acc[t][3] = 0.f;
    }

    #pragma unroll 1
    for (int kc = 0; kc < 16; ++kc) {
        const int k = kc * 8;
        uint32_t ahi[4][4], alo[4][4];
        #pragma unroll
        for (int ti = 0; ti < 4; ++ti) {
            const float* rp = sb + (16 * ti + lr) * ROW_STRIDE + k + lc;
            float v0 = rp[0];
            float v1 = rp[8 * ROW_STRIDE];
            float v2 = rp[4];
            float v3 = rp[8 * ROW_STRIDE + 4];
            ahi[ti][0] = f2tf32(v0);
            alo[ti][0] = __float_as_uint(v0 - __uint_as_float(ahi[ti][0]));
            ahi[ti][1] = f2tf32(v1);
            alo[ti][1] = __float_as_uint(v1 - __uint_as_float(ahi[ti][1]));
            ahi[ti][2] = f2tf32(v2);
            alo[ti][2] = __float_as_uint(v2 - __uint_as_float(ahi[ti][2]));
            ahi[ti][3] = f2tf32(v3);
            alo[ti][3] = __float_as_uint(v3 - __uint_as_float(ahi[ti][3]));
        }
        #pragma unroll
        for (int ti = 0; ti < 4; ++ti) {
            #pragma unroll
            for (int tj = 0; tj < 8; ++tj) {
                if (tj >= 2 * ti) {
                    const int t  = TOFF[ti] + tj - 2 * ti;
                    const int tb = tj >> 1, sel = tj & 1;
                    // B fragment == A-fragment regs of stripe tb (C = A·A^T)
                    uint32_t b0h = ahi[tb][sel], b1h = ahi[tb][sel + 2];
                    uint32_t b0l = alo[tb][sel], b1l = alo[tb][sel + 2];
                    mma8(acc[t], ahi[ti], b0h, b1h);   // hi·hi
                    mma8(acc[t], ahi[ti], b0l, b1l);   // hi·lo
                    mma8(acc[t], alo[ti], b0h, b1h);   // lo·hi
                }
            }
        }
    }

    // ---- epilogue: scatter triu into own smem region, then coalesced copy ----
    // idx(i,j) = i*63 - i*(i-1)/2 + (j - i - 1);  base(i) = idx(i,0..)-j form
    #pragma unroll
    for (int ti = 0; ti < 4; ++ti) {
        #pragma unroll
        for (int tj = 0; tj < 8; ++tj) {
            if (tj >= 2 * ti) {
                const int t  = TOFF[ti] + tj - 2 * ti;
                const int i0 = 16 * ti + lr, i1 = i0 + 8;
                const int j0 = 8 * tj + 2 * lc, j1 = j0 + 1;
                const int base0 = i0 * 63 - (i0 * (i0 - 1)) / 2 - i0 - 1;
                const int base1 = i1 * 63 - (i1 * (i1 - 1)) / 2 - i1 - 1;
                if (tj >= 2 * ti + 2) {           // fully above diagonal
                    sb[base0 + j0] = acc[t][0];
                    sb[base0 + j1] = acc[t][1];
                    sb[base1 + j0] = acc[t][2];
                    sb[base1 + j1] = acc[t][3];
                } else {                           // diagonal-straddling tiles
                    if (j0 > i0) sb[base0 + j0] = acc[t][0];
                    if (j1 > i0) sb[base0 + j1] = acc[t][1];
                    if (j0 > i1) sb[base1 + j0] = acc[t][2];
                    if (j1 > i1) sb[base1 + j1] = acc[t][3];
                }
            }
        }
    }
    __syncwarp();

    float* ob = out + (size_t)(b0 + wid) * OUT_PER_B;
    const float4* sv = reinterpret_cast<const float4*>(sb);
    for (int t = lane; t < OUT_PER_B / 4; t += 32) {   // 504 float4
        reinterpret_cast<float4*>(ob)[t] = sv[t];
    }
}

extern "C" void kernel_launch(void* const* d_in, const int* in_sizes, int n_in,
                              void* d_out, int out_size) {
    (void)in_sizes; (void)n_in; (void)out_size;
    const float* x = (const float*)d_in[0];
    float* out = (float*)d_out;

    const int smem = BATCHES * BATCH_SM * sizeof(float);   // 67584 B
    cudaFuncSetAttribute(interaction_mma,
                         cudaFuncAttributeMaxDynamicSharedMemorySize, smem);
    interaction_mma<<<B_TOTAL / BATCHES, THREADS, smem>>>(x, out);
}